// round 14
// baseline (speedup 1.0000x reference)
#include <cuda_runtime.h>
#include <cuda_fp16.h>
#include <math.h>
#include <stdint.h>

// ---------------- problem constants ----------------
#define NN   50000
#define EE   800000
#define EP   (EE + NN)
#define KIN  128
#define C1   256              // 8 heads * 32
#define NH   8
#define HD   32
#define NC   10
#define NEG  0.2f
#define GRID1 296             // 2 persistent CTAs per SM

// ---------------- scratch globals (zero-initialized at module load) ----------
__device__ __align__(256) __half g_h1h[(size_t)NN * C1];       // x@W1 in fp16
__device__ __align__(256) __half g_h1outh[(size_t)NN * C1];    // layer-1 out fp16
__device__ __align__(256) float  g_as1[NN * NH];
__device__ __align__(256) float  g_ad1[NN * NH];
__device__ __align__(256) float  g_h2[NN * 12];
__device__ __align__(256) __half g_Wh[C1 * KIN];               // W1^T fp16 [n][k]
__device__ __align__(256) int    g_rowptr[NN + 1];
__device__ __align__(256) int    g_cursor[NN];
__device__ __align__(256) int    g_counts[NN];                 // zero by init/scatter
__device__ __align__(256) int    g_esrc[EP];
__device__ __align__(256) int    g_bsums[256];

// ---------------- small helpers ----------------
__device__ __forceinline__ int eidx(const void* p, long long i, int is64) {
    return is64 ? (int)((const long long*)p)[i] : ((const int*)p)[i];
}
__device__ __forceinline__ float lrelu(float x) { return x > 0.f ? x : NEG * x; }
__device__ __forceinline__ float elu1(float x)  { return x > 0.f ? x : (__expf(x) - 1.f); }
__device__ __forceinline__ uint2 pack4h(float4 v) {
    __half2 a = __floats2half2_rn(v.x, v.y);
    __half2 b = __floats2half2_rn(v.z, v.w);
    return make_uint2(*(uint32_t*)&a, *(uint32_t*)&b);
}
// per-block dtype sniff: 64 in-range int64s <=> data really is int64
__device__ __forceinline__ int sniff64(const void* ei) {
    const long long* p = (const long long*)ei;
    int ok = 1;
#pragma unroll 8
    for (int q = 0; q < 64; q++) {
        long long v = p[q];
        if (v < 0 || v >= NN) ok = 0;
    }
    return ok;
}

// ---------------- launch 1: histogram + W1 transpose (fused) -----------------
__global__ void k_prep(const void* ei, const float* __restrict__ W1) {
    __shared__ int s_is64;
    if (threadIdx.x == 0) s_is64 = sniff64(ei);
    int i = blockIdx.x * blockDim.x + threadIdx.x;
    if (i < KIN * C1) {
        int k = i >> 8, n = i & 255;
        g_Wh[n * KIN + k] = __float2half(W1[i]);   // W1[k][n] row-major
    }
    __syncthreads();
    if (i < EP) {
        int is64 = s_is64;
        int d = (i < EE) ? eidx(ei, (long long)EE + i, is64) : (i - EE);
        atomicAdd(&g_counts[d], 1);
    }
}

// ---------------- launch 2: per-block sums ----------------
__global__ void k_scan1() {
    __shared__ int s[256];
    int t = threadIdx.x;
    int i = blockIdx.x * 256 + t;
    s[t] = (i < NN) ? g_counts[i] : 0;
    __syncthreads();
    for (int o = 128; o > 0; o >>= 1) {
        if (t < o) s[t] += s[t + o];
        __syncthreads();
    }
    if (t == 0) g_bsums[blockIdx.x] = s[0];
}

// ---------------- launch 3: fused global-offset + intra-block scan -----------
__global__ void k_scan3() {
    __shared__ int s[256];
    __shared__ int s_boff;
    int t = threadIdx.x;
    // local inclusive scan of the 196 block sums (every block redoes it; trivial)
    int v = (t < 196) ? g_bsums[t] : 0;
    s[t] = v;
    __syncthreads();
    for (int o = 1; o < 256; o <<= 1) {
        int x = (t >= o) ? s[t - o] : 0;
        __syncthreads();
        s[t] += x;
        __syncthreads();
    }
    if (t == 0) s_boff = (blockIdx.x == 0) ? 0 : s[blockIdx.x - 1];
    __syncthreads();
    int boff = s_boff;
    __syncthreads();                    // everyone has boff; s[] reusable
    // intra-block exclusive scan of counts
    int i = blockIdx.x * 256 + t;
    int c = (i < NN) ? g_counts[i] : 0;
    s[t] = c;
    __syncthreads();
    for (int o = 1; o < 256; o <<= 1) {
        int x = (t >= o) ? s[t - o] : 0;
        __syncthreads();
        s[t] += x;
        __syncthreads();
    }
    int excl = s[t] - c + boff;
    if (i < NN) { g_rowptr[i] = excl; g_cursor[i] = excl; }
    if (i == 0) g_rowptr[NN] = EP;
}

// ---------------- launch 4: scatter + counts re-zero (for next replay) -------
__global__ void k_scatter(const void* ei) {
    __shared__ int s_is64;
    if (threadIdx.x == 0) s_is64 = sniff64(ei);
    __syncthreads();
    int i = blockIdx.x * blockDim.x + threadIdx.x;
    if (i < NN) g_counts[i] = 0;        // restore invariant for next replay
    if (i >= EP) return;
    int is64 = s_is64;
    int s, d;
    if (i < EE) {
        s = eidx(ei, i, is64);
        d = eidx(ei, (long long)EE + i, is64);
    } else {
        s = d = i - EE;
    }
    int pos = atomicAdd(&g_cursor[d], 1);
    g_esrc[pos] = s;
}

// ---------------- GEMM1 + attn-logits: persistent fp16 mma -------------------
// cp.async fp32 x -> smem fbuf; cvt -> fp16 hbuf between tiles. Single fbuf.
#define SAS 136                                  // fp16 row stride (halves)
#define SAF 132                                  // fp32 row stride (floats)
#define OFF_B  0
#define OFF_FA (256 * SAS * 2)                   // bytes: 69632
#define OFF_HA (OFF_FA + 32 * SAF * 4)           // 86528
#define SM_BYTES (OFF_HA + 32 * SAS * 2)         // 95232 B (~93 KB)

__device__ __forceinline__ uint32_t cvta_s(const void* p) {
    uint32_t a;
    asm("{ .reg .u64 t; cvta.to.shared.u64 t, %1; cvt.u32.u64 %0, t; }" : "=r"(a) : "l"(p));
    return a;
}
__device__ __forceinline__ void ldmx4(uint32_t r[4], uint32_t addr) {
    asm volatile("ldmatrix.sync.aligned.m8n8.x4.shared.b16 {%0,%1,%2,%3}, [%4];"
                 : "=r"(r[0]), "=r"(r[1]), "=r"(r[2]), "=r"(r[3]) : "r"(addr));
}
__device__ __forceinline__ void mma16816(float c[4], const uint32_t a[4], const uint32_t b[2]) {
    asm volatile(
        "mma.sync.aligned.m16n8k16.row.col.f32.f16.f16.f32 "
        "{%0,%1,%2,%3},{%4,%5,%6,%7},{%8,%9},{%0,%1,%2,%3};"
        : "+f"(c[0]), "+f"(c[1]), "+f"(c[2]), "+f"(c[3])
        : "r"(a[0]), "r"(a[1]), "r"(a[2]), "r"(a[3]), "r"(b[0]), "r"(b[1]));
}
#define CPASYNC16(dst, src) \
    asm volatile("cp.async.ca.shared.global [%0], [%1], 16;" :: "r"(dst), "l"(src))
#define CPCOMMIT() asm volatile("cp.async.commit_group;" ::: "memory")
#define CPWAIT0()  asm volatile("cp.async.wait_group 0;" ::: "memory")

__device__ __forceinline__ void issue_a(uint32_t sbase, const float* __restrict__ x,
                                        int t, int arow, int acol) {
    int gr = t * 32 + arow;
    if (gr >= NN) gr = NN - 1;                   // clamp; rows >= NN never stored
    const float* src = x + (size_t)gr * KIN + acol;
    uint32_t dst = sbase + OFF_FA + (uint32_t)((arow * SAF + acol) * 4);
#pragma unroll
    for (int j = 0; j < 4; j++) CPASYNC16(dst + j * 16, src + j * 4);
}

__device__ __forceinline__ void cvt_a(char* smc, int tid) {
    const float* fb = (const float*)(smc + OFF_FA);
    __half* hb = (__half*)(smc + OFF_HA);
#pragma unroll
    for (int j = tid; j < 1024; j += 256) {
        int row = j >> 5, c4 = (j & 31) * 4;
        float4 v = *(const float4*)(fb + row * SAF + c4);
        *(uint2*)(hb + row * SAS + c4) = pack4h(v);
    }
}

__global__ void __launch_bounds__(256, 2) k_hmma1(const float* __restrict__ x,
                                                  const float* __restrict__ asrc,
                                                  const float* __restrict__ adst) {
    extern __shared__ char smc[];
    __half* smB = (__half*)smc;
    uint32_t sbase = cvta_s(smc);
    int tid = threadIdx.x;
    int wid = tid >> 5, lane = tid & 31;
    int wm = wid >> 2, wn = wid & 3;           // 2x4 warps: 16 rows x 64 cols each
    int cx = blockIdx.x;
    int hA = 2 * wn, hB = 2 * wn + 1;

    int arow = tid >> 3;                       // 0..31
    int acol = (tid & 7) * 16;                 // floats
    const int T = (NN + 31) / 32;              // 1563

    int t = cx;
    issue_a(sbase, x, t, arow, acol);
    CPCOMMIT();

    for (int i = tid; i < 4096; i += 256) {
        int n = i >> 4, k8 = (i & 15) * 8;
        *(uint4*)(smB + n * SAS + k8) =
            *(const uint4*)(g_Wh + (size_t)n * KIN + k8);
    }

    float saA[8], daA[8], saB[8], daB[8];
#pragma unroll
    for (int j8 = 0; j8 < 4; j8++)
#pragma unroll
        for (int j = 0; j < 2; j++) {
            int c = j8 * 8 + (lane & 3) * 2 + j;
            saA[j8 * 2 + j] = asrc[hA * HD + c];
            daA[j8 * 2 + j] = adst[hA * HD + c];
            saB[j8 * 2 + j] = asrc[hB * HD + c];
            daB[j8 * 2 + j] = adst[hB * HD + c];
        }

    int blk = lane >> 3, rowin = lane & 7;
    int a_r = (blk & 1) * 8 + rowin, a_c = (blk >> 1) * 8;
    int b_n = (blk >> 1) * 8 + rowin, b_c = (blk & 1) * 8;

    CPWAIT0();
    __syncthreads();
    cvt_a(smc, tid);
    __syncthreads();

    for (; t < T; t += GRID1) {
        int tn = t + GRID1;
        bool have_next = (tn < T);
        if (have_next) {
            issue_a(sbase, x, tn, arow, acol);
            CPCOMMIT();
        }

        float acc[8][4] = {};
#pragma unroll
        for (int ks = 0; ks < 8; ks++) {
            int k0 = ks * 16;
            uint32_t a4[4], b4[4][4];
            uint32_t aoff = sbase + OFF_HA +
                            (uint32_t)(((wm * 16 + a_r) * SAS + k0 + a_c) * 2);
            ldmx4(a4, aoff);
#pragma unroll
            for (int pr = 0; pr < 4; pr++) {
                int nB = wn * 64 + pr * 16 + b_n;
                uint32_t boff = sbase + (uint32_t)((nB * SAS + k0 + b_c) * 2);
                ldmx4(b4[pr], boff);
            }
#pragma unroll
            for (int nt = 0; nt < 8; nt++)
                mma16816(acc[nt], a4, &b4[nt >> 1][(nt & 1) * 2]);
        }

        // ---- fused asd from fp32 accumulators ----
        {
            float sA0 = 0.f, dA0 = 0.f, sA8 = 0.f, dA8 = 0.f;
            float sB0 = 0.f, dB0 = 0.f, sB8 = 0.f, dB8 = 0.f;
#pragma unroll
            for (int j8 = 0; j8 < 4; j8++) {
                sA0 += acc[j8][0] * saA[j8 * 2] + acc[j8][1] * saA[j8 * 2 + 1];
                dA0 += acc[j8][0] * daA[j8 * 2] + acc[j8][1] * daA[j8 * 2 + 1];
                sA8 += acc[j8][2] * saA[j8 * 2] + acc[j8][3] * saA[j8 * 2 + 1];
                dA8 += acc[j8][2] * daA[j8 * 2] + acc[j8][3] * daA[j8 * 2 + 1];
                sB0 += acc[4 + j8][0] * saB[j8 * 2] + acc[4 + j8][1] * saB[j8 * 2 + 1];
                dB0 += acc[4 + j8][0] * daB[j8 * 2] + acc[4 + j8][1] * daB[j8 * 2 + 1];
                sB8 += acc[4 + j8][2] * saB[j8 * 2] + acc[4 + j8][3] * saB[j8 * 2 + 1];
                dB8 += acc[4 + j8][2] * daB[j8 * 2] + acc[4 + j8][3] * daB[j8 * 2 + 1];
            }
#pragma unroll
            for (int o = 1; o <= 2; o <<= 1) {
                sA0 += __shfl_xor_sync(0xffffffffu, sA0, o);
                dA0 += __shfl_xor_sync(0xffffffffu, dA0, o);
                sA8 += __shfl_xor_sync(0xffffffffu, sA8, o);
                dA8 += __shfl_xor_sync(0xffffffffu, dA8, o);
                sB0 += __shfl_xor_sync(0xffffffffu, sB0, o);
                dB0 += __shfl_xor_sync(0xffffffffu, dB0, o);
                sB8 += __shfl_xor_sync(0xffffffffu, sB8, o);
                dB8 += __shfl_xor_sync(0xffffffffu, dB8, o);
            }
            if ((lane & 3) == 0) {
                int r = t * 32 + wm * 16 + (lane >> 2);
                if (r < NN) {
                    g_as1[r * NH + hA] = sA0; g_ad1[r * NH + hA] = dA0;
                    g_as1[r * NH + hB] = sB0; g_ad1[r * NH + hB] = dB0;
                }
                if (r + 8 < NN) {
                    g_as1[(r + 8) * NH + hA] = sA8; g_ad1[(r + 8) * NH + hA] = dA8;
                    g_as1[(r + 8) * NH + hB] = sB8; g_ad1[(r + 8) * NH + hB] = dB8;
                }
            }
        }

        // ---- store fp16 h1 ----
        int r = t * 32 + wm * 16 + (lane >> 2);
#pragma unroll
        for (int nt = 0; nt < 8; nt++) {
            int gc = wn * 64 + nt * 8 + (lane & 3) * 2;
            if (r < NN)
                *(__half2*)(g_h1h + (size_t)r * C1 + gc) =
                    __floats2half2_rn(acc[nt][0], acc[nt][1]);
            if (r + 8 < NN)
                *(__half2*)(g_h1h + (size_t)(r + 8) * C1 + gc) =
                    __floats2half2_rn(acc[nt][2], acc[nt][3]);
        }

        if (have_next) CPWAIT0();
        __syncthreads();
        if (have_next) cvt_a(smc, tid);
        __syncthreads();
    }
}

// ---------------- layer-1 aggregation: 2 warps/node --------------------------
__global__ void k_agg1(const float* __restrict__ b1) {
    int gw = (blockIdx.x * blockDim.x + threadIdx.x) >> 5;
    if (gw >= NN * 2) return;
    int lane = threadIdx.x & 31;
    int n = gw >> 1, w = gw & 1;
    int head = w * 4 + (lane >> 3);
    int beg = g_rowptr[n], end = g_rowptr[n + 1];
    float ad = g_ad1[n * NH + head];
    int off = w * 32 + lane;                   // uint2 index into a 256-ch row

    float4 acc = make_float4(0.f, 0.f, 0.f, 0.f);
    float den = 0.f;
    int i = beg;
    for (; i + 3 < end; i += 4) {
        int s0 = g_esrc[i], s1 = g_esrc[i + 1], s2 = g_esrc[i + 2], s3 = g_esrc[i + 3];
        float a0 = g_as1[s0 * NH + head], a1 = g_as1[s1 * NH + head];
        float a2 = g_as1[s2 * NH + head], a3 = g_as1[s3 * NH + head];
        uint2 u0 = ((const uint2*)(g_h1h + (size_t)s0 * C1))[off];
        uint2 u1 = ((const uint2*)(g_h1h + (size_t)s1 * C1))[off];
        uint2 u2 = ((const uint2*)(g_h1h + (size_t)s2 * C1))[off];
        uint2 u3 = ((const uint2*)(g_h1h + (size_t)s3 * C1))[off];
        float w0 = __expf(lrelu(a0 + ad)), w1 = __expf(lrelu(a1 + ad));
        float w2 = __expf(lrelu(a2 + ad)), w3 = __expf(lrelu(a3 + ad));
        den += w0 + w1 + w2 + w3;
        float2 f;
        f = __half22float2(*(__half2*)&u0.x); acc.x += w0 * f.x; acc.y += w0 * f.y;
        f = __half22float2(*(__half2*)&u0.y); acc.z += w0 * f.x; acc.w += w0 * f.y;
        f = __half22float2(*(__half2*)&u1.x); acc.x += w1 * f.x; acc.y += w1 * f.y;
        f = __half22float2(*(__half2*)&u1.y); acc.z += w1 * f.x; acc.w += w1 * f.y;
        f = __half22float2(*(__half2*)&u2.x); acc.x += w2 * f.x; acc.y += w2 * f.y;
        f = __half22float2(*(__half2*)&u2.y); acc.z += w2 * f.x; acc.w += w2 * f.y;
        f = __half22float2(*(__half2*)&u3.x); acc.x += w3 * f.x; acc.y += w3 * f.y;
        f = __half22float2(*(__half2*)&u3.y); acc.z += w3 * f.x; acc.w += w3 * f.y;
    }
    for (; i < end; i++) {
        int s = g_esrc[i];
        float a = g_as1[s * NH + head];
        uint2 u = ((const uint2*)(g_h1h + (size_t)s * C1))[off];
        float wgt = __expf(lrelu(a + ad));
        den += wgt;
        float2 f;
        f = __half22float2(*(__half2*)&u.x); acc.x += wgt * f.x; acc.y += wgt * f.y;
        f = __half22float2(*(__half2*)&u.y); acc.z += wgt * f.x; acc.w += wgt * f.y;
    }
    float inv = 1.f / den;
    float4 bb = ((const float4*)b1)[off];
    float4 o;
    o.x = elu1(acc.x * inv + bb.x); o.y = elu1(acc.y * inv + bb.y);
    o.z = elu1(acc.z * inv + bb.z); o.w = elu1(acc.w * inv + bb.w);
    ((uint2*)(g_h1outh + (size_t)n * C1))[off] = pack4h(o);
}

// ---------------- GEMM2 (fused W2aug, fp16 input) ----------------------------
__global__ void k_gemm2(const float* __restrict__ W2,
                        const float* __restrict__ as2,
                        const float* __restrict__ ad2) {
    __shared__ float Ws[C1 * 12];
    for (int i = threadIdx.x; i < C1; i += blockDim.x) {
        float s = 0.f, d = 0.f;
#pragma unroll
        for (int c = 0; c < NC; c++) {
            float w = W2[i * NC + c];
            Ws[i * 12 + c] = w;
            s += w * as2[c];
            d += w * ad2[c];
        }
        Ws[i * 12 + 10] = s;
        Ws[i * 12 + 11] = d;
    }
    __syncthreads();
    int n = blockIdx.x * blockDim.x + threadIdx.x;
    if (n >= NN) return;
    float acc[12];
#pragma unroll
    for (int c = 0; c < 12; c++) acc[c] = 0.f;
    const uint4* xp = (const uint4*)(g_h1outh + (size_t)n * C1);
    for (int q = 0; q < 32; q++) {
        uint4 u = xp[q];
        float f[8];
        float2 t0 = __half22float2(*(__half2*)&u.x);
        float2 t1 = __half22float2(*(__half2*)&u.y);
        float2 t2 = __half22float2(*(__half2*)&u.z);
        float2 t3 = __half22float2(*(__half2*)&u.w);
        f[0] = t0.x; f[1] = t0.y; f[2] = t1.x; f[3] = t1.y;
        f[4] = t2.x; f[5] = t2.y; f[6] = t3.x; f[7] = t3.y;
        const float* w = &Ws[(q * 8) * 12];
#pragma unroll
        for (int k = 0; k < 8; k++)
#pragma unroll
            for (int c = 0; c < 12; c++)
                acc[c] += f[k] * w[k * 12 + c];
    }
#pragma unroll
    for (int c = 0; c < 12; c++) g_h2[n * 12 + c] = acc[c];
}

// ---------------- layer-2 agg + log-softmax ----------------
__global__ void k_agg2(const float* __restrict__ b2, float* __restrict__ out) {
    int warp = (blockIdx.x * blockDim.x + threadIdx.x) >> 5;
    if (warp >= NN) return;
    int lane = threadIdx.x & 31;
    int n = warp;
    float ad2v = g_h2[n * 12 + 11];
    int beg = g_rowptr[n], end = g_rowptr[n + 1];

    float4 A = make_float4(0.f, 0.f, 0.f, 0.f);
    float4 Bv = make_float4(0.f, 0.f, 0.f, 0.f);
    float c8 = 0.f, c9 = 0.f, den = 0.f;
    for (int i = beg + lane; i < end; i += 32) {
        int s = g_esrc[i];
        const float4* hp = (const float4*)(g_h2 + (size_t)s * 12);
        float4 r0 = hp[0], r1 = hp[1], r2 = hp[2];
        float w = __expf(lrelu(r2.z + ad2v));
        den += w;
        A.x += w * r0.x; A.y += w * r0.y; A.z += w * r0.z; A.w += w * r0.w;
        Bv.x += w * r1.x; Bv.y += w * r1.y; Bv.z += w * r1.z; Bv.w += w * r1.w;
        c8 += w * r2.x; c9 += w * r2.y;
    }
#pragma unroll
    for (int o = 16; o > 0; o >>= 1) {
        A.x += __shfl_xor_sync(0xffffffffu, A.x, o);
        A.y += __shfl_xor_sync(0xffffffffu, A.y, o);
        A.z += __shfl_xor_sync(0xffffffffu, A.z, o);
        A.w += __shfl_xor_sync(0xffffffffu, A.w, o);
        Bv.x += __shfl_xor_sync(0xffffffffu, Bv.x, o);
        Bv.y += __shfl_xor_sync(0xffffffffu, Bv.y, o);
        Bv.z += __shfl_xor_sync(0xffffffffu, Bv.z, o);
        Bv.w += __shfl_xor_sync(0xffffffffu, Bv.w, o);
        c8  += __shfl_xor_sync(0xffffffffu, c8, o);
        c9  += __shfl_xor_sync(0xffffffffu, c9, o);
        den += __shfl_xor_sync(0xffffffffu, den, o);
    }
    if (lane == 0) {
        float inv = 1.f / den;
        float v[NC];
        v[0] = A.x * inv + b2[0]; v[1] = A.y * inv + b2[1];
        v[2] = A.z * inv + b2[2]; v[3] = A.w * inv + b2[3];
        v[4] = Bv.x * inv + b2[4]; v[5] = Bv.y * inv + b2[5];
        v[6] = Bv.z * inv + b2[6]; v[7] = Bv.w * inv + b2[7];
        v[8] = c8 * inv + b2[8];  v[9] = c9 * inv + b2[9];
        float mx = v[0];
#pragma unroll
        for (int c = 1; c < NC; c++) mx = fmaxf(mx, v[c]);
        float sm = 0.f;
#pragma unroll
        for (int c = 0; c < NC; c++) sm += __expf(v[c] - mx);
        float l = mx + __logf(sm);
#pragma unroll
        for (int c = 0; c < NC; c++) out[(size_t)n * NC + c] = v[c] - l;
    }
}

// ---------------- launch ----------------
extern "C" void kernel_launch(void* const* d_in, const int* in_sizes, int n_in,
                              void* d_out, int out_size) {
    const float* x   = (const float*)d_in[0];
    const void*  ei  = d_in[1];
    const float* W1  = (const float*)d_in[2];
    const float* as1 = (const float*)d_in[3];
    const float* ad1 = (const float*)d_in[4];
    const float* b1  = (const float*)d_in[5];
    const float* W2  = (const float*)d_in[6];
    const float* as2 = (const float*)d_in[7];
    const float* ad2 = (const float*)d_in[8];
    const float* b2  = (const float*)d_in[9];
    float* out = (float*)d_out;

    cudaFuncSetAttribute(k_hmma1, cudaFuncAttributeMaxDynamicSharedMemorySize, SM_BYTES);

    k_prep<<<(EP + 255) / 256, 256>>>(ei, W1);              // 1 (hist + W1^T)
    k_scan1<<<196, 256>>>();                                // 2
    k_scan3<<<196, 256>>>();                                // 3 (fused scan2+3)
    k_scatter<<<(EP + 255) / 256, 256>>>(ei);               // 4 <- ncu slot
    k_hmma1<<<GRID1, 256, SM_BYTES>>>(x, as1, ad1);         // 5
    k_agg1<<<(NN * 2 + 7) / 8, 256>>>(b1);                  // 6
    k_gemm2<<<(NN + 127) / 128, 128>>>(W2, as2, ad2);       // 7
    k_agg2<<<(NN + 7) / 8, 256>>>(b2, out);                 // 8
}

// round 15
// speedup vs baseline: 1.1039x; 1.1039x over previous
#include <cuda_runtime.h>
#include <cuda_fp16.h>
#include <math.h>
#include <stdint.h>

// ---------------- problem constants ----------------
#define NN   50000
#define EE   800000
#define EP   (EE + NN)
#define KIN  128
#define C1   256              // 8 heads * 32
#define NH   8
#define HD   32
#define NC   10
#define NEG  0.2f
#define GRID1 296             // 2 persistent CTAs per SM

// ---------------- scratch globals (zero-initialized at module load) ----------
__device__ __align__(256) __half g_h1h[(size_t)NN * C1];       // x@W1 in fp16
__device__ __align__(256) __half g_h1outh[(size_t)NN * C1];    // layer-1 out fp16
__device__ __align__(256) float  g_as1[NN * NH];
__device__ __align__(256) float  g_ad1[NN * NH];
__device__ __align__(256) float  g_h2[NN * 12];
__device__ __align__(256) __half g_Wh[C1 * KIN];               // W1^T fp16 [n][k]
__device__ __align__(256) int    g_rowptr[NN + 1];
__device__ __align__(256) int    g_cursor[NN];
__device__ __align__(256) int    g_counts[NN];                 // zero by init/scatter
__device__ __align__(256) int    g_esrc[EP];
__device__ __align__(256) int    g_bsums[256];

// ---------------- small helpers ----------------
__device__ __forceinline__ int eidx(const void* p, long long i, int is64) {
    return is64 ? (int)((const long long*)p)[i] : ((const int*)p)[i];
}
__device__ __forceinline__ float lrelu(float x) { return x > 0.f ? x : NEG * x; }
__device__ __forceinline__ float elu1(float x)  { return x > 0.f ? x : (__expf(x) - 1.f); }
__device__ __forceinline__ uint2 pack4h(float4 v) {
    __half2 a = __floats2half2_rn(v.x, v.y);
    __half2 b = __floats2half2_rn(v.z, v.w);
    return make_uint2(*(uint32_t*)&a, *(uint32_t*)&b);
}
__device__ __forceinline__ int sniff64(const void* ei) {
    const long long* p = (const long long*)ei;
    int ok = 1;
#pragma unroll 8
    for (int q = 0; q < 64; q++) {
        long long v = p[q];
        if (v < 0 || v >= NN) ok = 0;
    }
    return ok;
}

// ---------------- launch 1: histogram + W1 transpose (fused) -----------------
__global__ void k_prep(const void* ei, const float* __restrict__ W1) {
    __shared__ int s_is64;
    if (threadIdx.x == 0) s_is64 = sniff64(ei);
    int i = blockIdx.x * blockDim.x + threadIdx.x;
    if (i < KIN * C1) {
        int k = i >> 8, n = i & 255;
        g_Wh[n * KIN + k] = __float2half(W1[i]);   // W1[k][n] row-major
    }
    __syncthreads();
    if (i < EP) {
        int is64 = s_is64;
        int d = (i < EE) ? eidx(ei, (long long)EE + i, is64) : (i - EE);
        atomicAdd(&g_counts[d], 1);
    }
}

// ---------------- launch 2: per-block sums ----------------
__global__ void k_scan1() {
    __shared__ int s[256];
    int t = threadIdx.x;
    int i = blockIdx.x * 256 + t;
    s[t] = (i < NN) ? g_counts[i] : 0;
    __syncthreads();
    for (int o = 128; o > 0; o >>= 1) {
        if (t < o) s[t] += s[t + o];
        __syncthreads();
    }
    if (t == 0) g_bsums[blockIdx.x] = s[0];
}

// ---------------- launch 3: fused global-offset + intra-block scan -----------
__global__ void k_scan3() {
    __shared__ int s[256];
    __shared__ int s_boff;
    int t = threadIdx.x;
    int v = (t < 196) ? g_bsums[t] : 0;
    s[t] = v;
    __syncthreads();
    for (int o = 1; o < 256; o <<= 1) {
        int x = (t >= o) ? s[t - o] : 0;
        __syncthreads();
        s[t] += x;
        __syncthreads();
    }
    if (t == 0) s_boff = (blockIdx.x == 0) ? 0 : s[blockIdx.x - 1];
    __syncthreads();
    int boff = s_boff;
    __syncthreads();
    int i = blockIdx.x * 256 + t;
    int c = (i < NN) ? g_counts[i] : 0;
    s[t] = c;
    __syncthreads();
    for (int o = 1; o < 256; o <<= 1) {
        int x = (t >= o) ? s[t - o] : 0;
        __syncthreads();
        s[t] += x;
        __syncthreads();
    }
    int excl = s[t] - c + boff;
    if (i < NN) { g_rowptr[i] = excl; g_cursor[i] = excl; }
    if (i == 0) g_rowptr[NN] = EP;
}

// ---------------- launch 4: scatter + counts re-zero -------------------------
__global__ void k_scatter(const void* ei) {
    __shared__ int s_is64;
    if (threadIdx.x == 0) s_is64 = sniff64(ei);
    __syncthreads();
    int i = blockIdx.x * blockDim.x + threadIdx.x;
    if (i < NN) g_counts[i] = 0;        // restore invariant for next replay
    if (i >= EP) return;
    int is64 = s_is64;
    int s, d;
    if (i < EE) {
        s = eidx(ei, i, is64);
        d = eidx(ei, (long long)EE + i, is64);
    } else {
        s = d = i - EE;
    }
    int pos = atomicAdd(&g_cursor[d], 1);
    g_esrc[pos] = s;
}

// ---------------- GEMM1 + attn-logits: persistent fp16 mma -------------------
#define SAS 136
#define SAF 132
#define OFF_B  0
#define OFF_FA (256 * SAS * 2)
#define OFF_HA (OFF_FA + 32 * SAF * 4)
#define SM_BYTES (OFF_HA + 32 * SAS * 2)        // 95232 B

__device__ __forceinline__ uint32_t cvta_s(const void* p) {
    uint32_t a;
    asm("{ .reg .u64 t; cvta.to.shared.u64 t, %1; cvt.u32.u64 %0, t; }" : "=r"(a) : "l"(p));
    return a;
}
__device__ __forceinline__ void ldmx4(uint32_t r[4], uint32_t addr) {
    asm volatile("ldmatrix.sync.aligned.m8n8.x4.shared.b16 {%0,%1,%2,%3}, [%4];"
                 : "=r"(r[0]), "=r"(r[1]), "=r"(r[2]), "=r"(r[3]) : "r"(addr));
}
__device__ __forceinline__ void mma16816(float c[4], const uint32_t a[4], const uint32_t b[2]) {
    asm volatile(
        "mma.sync.aligned.m16n8k16.row.col.f32.f16.f16.f32 "
        "{%0,%1,%2,%3},{%4,%5,%6,%7},{%8,%9},{%0,%1,%2,%3};"
        : "+f"(c[0]), "+f"(c[1]), "+f"(c[2]), "+f"(c[3])
        : "r"(a[0]), "r"(a[1]), "r"(a[2]), "r"(a[3]), "r"(b[0]), "r"(b[1]));
}
#define CPASYNC16(dst, src) \
    asm volatile("cp.async.ca.shared.global [%0], [%1], 16;" :: "r"(dst), "l"(src))
#define CPCOMMIT() asm volatile("cp.async.commit_group;" ::: "memory")
#define CPWAIT0()  asm volatile("cp.async.wait_group 0;" ::: "memory")

__device__ __forceinline__ void issue_a(uint32_t sbase, const float* __restrict__ x,
                                        int t, int arow, int acol) {
    int gr = t * 32 + arow;
    if (gr >= NN) gr = NN - 1;
    const float* src = x + (size_t)gr * KIN + acol;
    uint32_t dst = sbase + OFF_FA + (uint32_t)((arow * SAF + acol) * 4);
#pragma unroll
    for (int j = 0; j < 4; j++) CPASYNC16(dst + j * 16, src + j * 4);
}

__device__ __forceinline__ void cvt_a(char* smc, int tid) {
    const float* fb = (const float*)(smc + OFF_FA);
    __half* hb = (__half*)(smc + OFF_HA);
#pragma unroll
    for (int j = tid; j < 1024; j += 256) {
        int row = j >> 5, c4 = (j & 31) * 4;
        float4 v = *(const float4*)(fb + row * SAF + c4);
        *(uint2*)(hb + row * SAS + c4) = pack4h(v);
    }
}

__global__ void __launch_bounds__(256, 2) k_hmma1(const float* __restrict__ x,
                                                  const float* __restrict__ asrc,
                                                  const float* __restrict__ adst) {
    extern __shared__ char smc[];
    __half* smB = (__half*)smc;
    uint32_t sbase = cvta_s(smc);
    int tid = threadIdx.x;
    int wid = tid >> 5, lane = tid & 31;
    int wm = wid >> 2, wn = wid & 3;
    int cx = blockIdx.x;
    int hA = 2 * wn, hB = 2 * wn + 1;

    int arow = tid >> 3;
    int acol = (tid & 7) * 16;
    const int T = (NN + 31) / 32;

    int t = cx;
    issue_a(sbase, x, t, arow, acol);
    CPCOMMIT();

    for (int i = tid; i < 4096; i += 256) {
        int n = i >> 4, k8 = (i & 15) * 8;
        *(uint4*)(smB + n * SAS + k8) =
            *(const uint4*)(g_Wh + (size_t)n * KIN + k8);
    }

    float saA[8], daA[8], saB[8], daB[8];
#pragma unroll
    for (int j8 = 0; j8 < 4; j8++)
#pragma unroll
        for (int j = 0; j < 2; j++) {
            int c = j8 * 8 + (lane & 3) * 2 + j;
            saA[j8 * 2 + j] = asrc[hA * HD + c];
            daA[j8 * 2 + j] = adst[hA * HD + c];
            saB[j8 * 2 + j] = asrc[hB * HD + c];
            daB[j8 * 2 + j] = adst[hB * HD + c];
        }

    int blk = lane >> 3, rowin = lane & 7;
    int a_r = (blk & 1) * 8 + rowin, a_c = (blk >> 1) * 8;
    int b_n = (blk >> 1) * 8 + rowin, b_c = (blk & 1) * 8;

    CPWAIT0();
    __syncthreads();
    cvt_a(smc, tid);
    __syncthreads();

    for (; t < T; t += GRID1) {
        int tn = t + GRID1;
        bool have_next = (tn < T);
        if (have_next) {
            issue_a(sbase, x, tn, arow, acol);
            CPCOMMIT();
        }

        float acc[8][4] = {};
#pragma unroll
        for (int ks = 0; ks < 8; ks++) {
            int k0 = ks * 16;
            uint32_t a4[4], b4[4][4];
            uint32_t aoff = sbase + OFF_HA +
                            (uint32_t)(((wm * 16 + a_r) * SAS + k0 + a_c) * 2);
            ldmx4(a4, aoff);
#pragma unroll
            for (int pr = 0; pr < 4; pr++) {
                int nB = wn * 64 + pr * 16 + b_n;
                uint32_t boff = sbase + (uint32_t)((nB * SAS + k0 + b_c) * 2);
                ldmx4(b4[pr], boff);
            }
#pragma unroll
            for (int nt = 0; nt < 8; nt++)
                mma16816(acc[nt], a4, &b4[nt >> 1][(nt & 1) * 2]);
        }

        {
            float sA0 = 0.f, dA0 = 0.f, sA8 = 0.f, dA8 = 0.f;
            float sB0 = 0.f, dB0 = 0.f, sB8 = 0.f, dB8 = 0.f;
#pragma unroll
            for (int j8 = 0; j8 < 4; j8++) {
                sA0 += acc[j8][0] * saA[j8 * 2] + acc[j8][1] * saA[j8 * 2 + 1];
                dA0 += acc[j8][0] * daA[j8 * 2] + acc[j8][1] * daA[j8 * 2 + 1];
                sA8 += acc[j8][2] * saA[j8 * 2] + acc[j8][3] * saA[j8 * 2 + 1];
                dA8 += acc[j8][2] * daA[j8 * 2] + acc[j8][3] * daA[j8 * 2 + 1];
                sB0 += acc[4 + j8][0] * saB[j8 * 2] + acc[4 + j8][1] * saB[j8 * 2 + 1];
                dB0 += acc[4 + j8][0] * daB[j8 * 2] + acc[4 + j8][1] * daB[j8 * 2 + 1];
                sB8 += acc[4 + j8][2] * saB[j8 * 2] + acc[4 + j8][3] * saB[j8 * 2 + 1];
                dB8 += acc[4 + j8][2] * daB[j8 * 2] + acc[4 + j8][3] * daB[j8 * 2 + 1];
            }
#pragma unroll
            for (int o = 1; o <= 2; o <<= 1) {
                sA0 += __shfl_xor_sync(0xffffffffu, sA0, o);
                dA0 += __shfl_xor_sync(0xffffffffu, dA0, o);
                sA8 += __shfl_xor_sync(0xffffffffu, sA8, o);
                dA8 += __shfl_xor_sync(0xffffffffu, dA8, o);
                sB0 += __shfl_xor_sync(0xffffffffu, sB0, o);
                dB0 += __shfl_xor_sync(0xffffffffu, dB0, o);
                sB8 += __shfl_xor_sync(0xffffffffu, sB8, o);
                dB8 += __shfl_xor_sync(0xffffffffu, dB8, o);
            }
            if ((lane & 3) == 0) {
                int r = t * 32 + wm * 16 + (lane >> 2);
                if (r < NN) {
                    g_as1[r * NH + hA] = sA0; g_ad1[r * NH + hA] = dA0;
                    g_as1[r * NH + hB] = sB0; g_ad1[r * NH + hB] = dB0;
                }
                if (r + 8 < NN) {
                    g_as1[(r + 8) * NH + hA] = sA8; g_ad1[(r + 8) * NH + hA] = dA8;
                    g_as1[(r + 8) * NH + hB] = sB8; g_ad1[(r + 8) * NH + hB] = dB8;
                }
            }
        }

        int r = t * 32 + wm * 16 + (lane >> 2);
#pragma unroll
        for (int nt = 0; nt < 8; nt++) {
            int gc = wn * 64 + nt * 8 + (lane & 3) * 2;
            if (r < NN)
                *(__half2*)(g_h1h + (size_t)r * C1 + gc) =
                    __floats2half2_rn(acc[nt][0], acc[nt][1]);
            if (r + 8 < NN)
                *(__half2*)(g_h1h + (size_t)(r + 8) * C1 + gc) =
                    __floats2half2_rn(acc[nt][2], acc[nt][3]);
        }

        if (have_next) CPWAIT0();
        __syncthreads();
        if (have_next) cvt_a(smc, tid);
        __syncthreads();
    }
}

// ---------------- layer-1 aggregation: 1 warp/node, uint4 (8ch) per lane -----
// Lane owns channels [lane*8, lane*8+8) -> head = lane>>2. One 16B load/edge.
__global__ void k_agg1(const float* __restrict__ b1) {
    int warp = (blockIdx.x * blockDim.x + threadIdx.x) >> 5;
    if (warp >= NN) return;
    int lane = threadIdx.x & 31;
    int n = warp;
    int head = lane >> 2;              // 0..7
    int beg = g_rowptr[n], end = g_rowptr[n + 1];
    float ad = g_ad1[n * NH + head];

    float acc[8] = {};
    float den = 0.f;
    int i = beg;
    for (; i + 3 < end; i += 4) {
        int s0 = g_esrc[i], s1 = g_esrc[i + 1], s2 = g_esrc[i + 2], s3 = g_esrc[i + 3];
        float a0 = g_as1[s0 * NH + head], a1 = g_as1[s1 * NH + head];
        float a2 = g_as1[s2 * NH + head], a3 = g_as1[s3 * NH + head];
        uint4 u0 = ((const uint4*)(g_h1h + (size_t)s0 * C1))[lane];
        uint4 u1 = ((const uint4*)(g_h1h + (size_t)s1 * C1))[lane];
        uint4 u2 = ((const uint4*)(g_h1h + (size_t)s2 * C1))[lane];
        uint4 u3 = ((const uint4*)(g_h1h + (size_t)s3 * C1))[lane];
        float w0 = __expf(lrelu(a0 + ad)), w1 = __expf(lrelu(a1 + ad));
        float w2 = __expf(lrelu(a2 + ad)), w3 = __expf(lrelu(a3 + ad));
        den += w0 + w1 + w2 + w3;
        const uint32_t* p0 = (const uint32_t*)&u0;
        const uint32_t* p1 = (const uint32_t*)&u1;
        const uint32_t* p2 = (const uint32_t*)&u2;
        const uint32_t* p3 = (const uint32_t*)&u3;
#pragma unroll
        for (int q = 0; q < 4; q++) {
            float2 f0 = __half22float2(*(__half2*)&p0[q]);
            float2 f1 = __half22float2(*(__half2*)&p1[q]);
            float2 f2 = __half22float2(*(__half2*)&p2[q]);
            float2 f3 = __half22float2(*(__half2*)&p3[q]);
            acc[2 * q]     += w0 * f0.x + w1 * f1.x + w2 * f2.x + w3 * f3.x;
            acc[2 * q + 1] += w0 * f0.y + w1 * f1.y + w2 * f2.y + w3 * f3.y;
        }
    }
    for (; i < end; i++) {
        int s = g_esrc[i];
        float a = g_as1[s * NH + head];
        uint4 u = ((const uint4*)(g_h1h + (size_t)s * C1))[lane];
        float w = __expf(lrelu(a + ad));
        den += w;
        const uint32_t* p = (const uint32_t*)&u;
#pragma unroll
        for (int q = 0; q < 4; q++) {
            float2 f = __half22float2(*(__half2*)&p[q]);
            acc[2 * q]     += w * f.x;
            acc[2 * q + 1] += w * f.y;
        }
    }
    float inv = 1.f / den;
    float4 bb0 = ((const float4*)b1)[lane * 2];
    float4 bb1 = ((const float4*)b1)[lane * 2 + 1];
    float o[8];
    o[0] = elu1(acc[0] * inv + bb0.x); o[1] = elu1(acc[1] * inv + bb0.y);
    o[2] = elu1(acc[2] * inv + bb0.z); o[3] = elu1(acc[3] * inv + bb0.w);
    o[4] = elu1(acc[4] * inv + bb1.x); o[5] = elu1(acc[5] * inv + bb1.y);
    o[6] = elu1(acc[6] * inv + bb1.z); o[7] = elu1(acc[7] * inv + bb1.w);
    uint4 st;
    {
        __half2 h0 = __floats2half2_rn(o[0], o[1]);
        __half2 h1 = __floats2half2_rn(o[2], o[3]);
        __half2 h2 = __floats2half2_rn(o[4], o[5]);
        __half2 h3 = __floats2half2_rn(o[6], o[7]);
        st.x = *(uint32_t*)&h0; st.y = *(uint32_t*)&h1;
        st.z = *(uint32_t*)&h2; st.w = *(uint32_t*)&h3;
    }
    ((uint4*)(g_h1outh + (size_t)n * C1))[lane] = st;
}

// ---------------- GEMM2 (fused W2aug, fp16 input) ----------------------------
__global__ void k_gemm2(const float* __restrict__ W2,
                        const float* __restrict__ as2,
                        const float* __restrict__ ad2) {
    __shared__ float Ws[C1 * 12];
    for (int i = threadIdx.x; i < C1; i += blockDim.x) {
        float s = 0.f, d = 0.f;
#pragma unroll
        for (int c = 0; c < NC; c++) {
            float w = W2[i * NC + c];
            Ws[i * 12 + c] = w;
            s += w * as2[c];
            d += w * ad2[c];
        }
        Ws[i * 12 + 10] = s;
        Ws[i * 12 + 11] = d;
    }
    __syncthreads();
    int n = blockIdx.x * blockDim.x + threadIdx.x;
    if (n >= NN) return;
    float acc[12];
#pragma unroll
    for (int c = 0; c < 12; c++) acc[c] = 0.f;
    const uint4* xp = (const uint4*)(g_h1outh + (size_t)n * C1);
    for (int q = 0; q < 32; q++) {
        uint4 u = xp[q];
        float f[8];
        float2 t0 = __half22float2(*(__half2*)&u.x);
        float2 t1 = __half22float2(*(__half2*)&u.y);
        float2 t2 = __half22float2(*(__half2*)&u.z);
        float2 t3 = __half22float2(*(__half2*)&u.w);
        f[0] = t0.x; f[1] = t0.y; f[2] = t1.x; f[3] = t1.y;
        f[4] = t2.x; f[5] = t2.y; f[6] = t3.x; f[7] = t3.y;
        const float* w = &Ws[(q * 8) * 12];
#pragma unroll
        for (int k = 0; k < 8; k++)
#pragma unroll
            for (int c = 0; c < 12; c++)
                acc[c] += f[k] * w[k * 12 + c];
    }
#pragma unroll
    for (int c = 0; c < 12; c++) g_h2[n * 12 + c] = acc[c];
}

// ---------------- layer-2 agg + log-softmax ----------------
__global__ void k_agg2(const float* __restrict__ b2, float* __restrict__ out) {
    int warp = (blockIdx.x * blockDim.x + threadIdx.x) >> 5;
    if (warp >= NN) return;
    int lane = threadIdx.x & 31;
    int n = warp;
    float ad2v = g_h2[n * 12 + 11];
    int beg = g_rowptr[n], end = g_rowptr[n + 1];

    float4 A = make_float4(0.f, 0.f, 0.f, 0.f);
    float4 Bv = make_float4(0.f, 0.f, 0.f, 0.f);
    float c8 = 0.f, c9 = 0.f, den = 0.f;
    for (int i = beg + lane; i < end; i += 32) {
        int s = g_esrc[i];
        const float4* hp = (const float4*)(g_h2 + (size_t)s * 12);
        float4 r0 = hp[0], r1 = hp[1], r2 = hp[2];
        float w = __expf(lrelu(r2.z + ad2v));
        den += w;
        A.x += w * r0.x; A.y += w * r0.y; A.z += w * r0.z; A.w += w * r0.w;
        Bv.x += w * r1.x; Bv.y += w * r1.y; Bv.z += w * r1.z; Bv.w += w * r1.w;
        c8 += w * r2.x; c9 += w * r2.y;
    }
#pragma unroll
    for (int o = 16; o > 0; o >>= 1) {
        A.x += __shfl_xor_sync(0xffffffffu, A.x, o);
        A.y += __shfl_xor_sync(0xffffffffu, A.y, o);
        A.z += __shfl_xor_sync(0xffffffffu, A.z, o);
        A.w += __shfl_xor_sync(0xffffffffu, A.w, o);
        Bv.x += __shfl_xor_sync(0xffffffffu, Bv.x, o);
        Bv.y += __shfl_xor_sync(0xffffffffu, Bv.y, o);
        Bv.z += __shfl_xor_sync(0xffffffffu, Bv.z, o);
        Bv.w += __shfl_xor_sync(0xffffffffu, Bv.w, o);
        c8  += __shfl_xor_sync(0xffffffffu, c8, o);
        c9  += __shfl_xor_sync(0xffffffffu, c9, o);
        den += __shfl_xor_sync(0xffffffffu, den, o);
    }
    if (lane == 0) {
        float inv = 1.f / den;
        float v[NC];
        v[0] = A.x * inv + b2[0]; v[1] = A.y * inv + b2[1];
        v[2] = A.z * inv + b2[2]; v[3] = A.w * inv + b2[3];
        v[4] = Bv.x * inv + b2[4]; v[5] = Bv.y * inv + b2[5];
        v[6] = Bv.z * inv + b2[6]; v[7] = Bv.w * inv + b2[7];
        v[8] = c8 * inv + b2[8];  v[9] = c9 * inv + b2[9];
        float mx = v[0];
#pragma unroll
        for (int c = 1; c < NC; c++) mx = fmaxf(mx, v[c]);
        float sm = 0.f;
#pragma unroll
        for (int c = 0; c < NC; c++) sm += __expf(v[c] - mx);
        float l = mx + __logf(sm);
#pragma unroll
        for (int c = 0; c < NC; c++) out[(size_t)n * NC + c] = v[c] - l;
    }
}

// ---------------- launch ----------------
extern "C" void kernel_launch(void* const* d_in, const int* in_sizes, int n_in,
                              void* d_out, int out_size) {
    const float* x   = (const float*)d_in[0];
    const void*  ei  = d_in[1];
    const float* W1  = (const float*)d_in[2];
    const float* as1 = (const float*)d_in[3];
    const float* ad1 = (const float*)d_in[4];
    const float* b1  = (const float*)d_in[5];
    const float* W2  = (const float*)d_in[6];
    const float* as2 = (const float*)d_in[7];
    const float* ad2 = (const float*)d_in[8];
    const float* b2  = (const float*)d_in[9];
    float* out = (float*)d_out;

    cudaFuncSetAttribute(k_hmma1, cudaFuncAttributeMaxDynamicSharedMemorySize, SM_BYTES);

    k_prep<<<(EP + 255) / 256, 256>>>(ei, W1);              // 1
    k_scan1<<<196, 256>>>();                                // 2
    k_scan3<<<196, 256>>>();                                // 3
    k_scatter<<<(EP + 255) / 256, 256>>>(ei);               // 4 <- ncu slot
    k_hmma1<<<GRID1, 256, SM_BYTES>>>(x, as1, ad1);         // 5
    k_agg1<<<(NN + 7) / 8, 256>>>(b1);                      // 6
    k_gemm2<<<(NN + 127) / 128, 128>>>(W2, as2, ad2);       // 7
    k_agg2<<<(NN + 7) / 8, 256>>>(b2, out);                 // 8
}

// round 16
// speedup vs baseline: 1.1646x; 1.0550x over previous
#include <cuda_runtime.h>
#include <cuda_fp16.h>
#include <math.h>
#include <stdint.h>

// ---------------- problem constants ----------------
#define NN   50000
#define EE   800000
#define EP   (EE + NN)
#define KIN  128
#define C1   256              // 8 heads * 32
#define NH   8
#define HD   32
#define NC   10
#define NEG  0.2f
#define GRID1 296             // 2 persistent CTAs per SM

// ---------------- scratch globals (zero-initialized at module load) ----------
__device__ __align__(256) __half g_h1h[(size_t)NN * C1];       // x@W1 in fp16
__device__ __align__(256) __half g_h1outh[(size_t)NN * C1];    // layer-1 out fp16
__device__ __align__(256) float  g_as1[NN * NH];
__device__ __align__(256) float  g_ad1[NN * NH];
__device__ __align__(256) float  g_h2[NN * 12];
__device__ __align__(256) __half g_Wh[C1 * KIN];               // W1^T fp16 [n][k]
__device__ __align__(256) int    g_rowptr[NN + 1];
__device__ __align__(256) int    g_cursor[NN];
__device__ __align__(256) int    g_counts[NN];                 // zero by init/scatter
__device__ __align__(256) int    g_esrc[EP];
__device__ __align__(256) int    g_bsums[256];

// ---------------- small helpers ----------------
__device__ __forceinline__ int eidx(const void* p, long long i, int is64) {
    return is64 ? (int)((const long long*)p)[i] : ((const int*)p)[i];
}
__device__ __forceinline__ float lrelu(float x) { return x > 0.f ? x : NEG * x; }
__device__ __forceinline__ float elu1(float x)  { return x > 0.f ? x : (__expf(x) - 1.f); }
__device__ __forceinline__ uint2 pack4h(float4 v) {
    __half2 a = __floats2half2_rn(v.x, v.y);
    __half2 b = __floats2half2_rn(v.z, v.w);
    return make_uint2(*(uint32_t*)&a, *(uint32_t*)&b);
}
__device__ __forceinline__ int sniff64(const void* ei) {
    const long long* p = (const long long*)ei;
    int ok = 1;
#pragma unroll 8
    for (int q = 0; q < 64; q++) {
        long long v = p[q];
        if (v < 0 || v >= NN) ok = 0;
    }
    return ok;
}

// ---------------- launch 1: histogram + W1 transpose (fused) -----------------
__global__ void k_prep(const void* ei, const float* __restrict__ W1) {
    __shared__ int s_is64;
    if (threadIdx.x == 0) s_is64 = sniff64(ei);
    int i = blockIdx.x * blockDim.x + threadIdx.x;
    if (i < KIN * C1) {
        int k = i >> 8, n = i & 255;
        g_Wh[n * KIN + k] = __float2half(W1[i]);   // W1[k][n] row-major
    }
    __syncthreads();
    if (i < EP) {
        int is64 = s_is64;
        int d = (i < EE) ? eidx(ei, (long long)EE + i, is64) : (i - EE);
        atomicAdd(&g_counts[d], 1);
    }
}

// ---------------- launch 2: per-block sums ----------------
__global__ void k_scan1() {
    __shared__ int s[256];
    int t = threadIdx.x;
    int i = blockIdx.x * 256 + t;
    s[t] = (i < NN) ? g_counts[i] : 0;
    __syncthreads();
    for (int o = 128; o > 0; o >>= 1) {
        if (t < o) s[t] += s[t + o];
        __syncthreads();
    }
    if (t == 0) g_bsums[blockIdx.x] = s[0];
}

// ---------------- launch 3: fused global-offset + intra-block scan -----------
__global__ void k_scan3() {
    __shared__ int s[256];
    __shared__ int s_boff;
    int t = threadIdx.x;
    int v = (t < 196) ? g_bsums[t] : 0;
    s[t] = v;
    __syncthreads();
    for (int o = 1; o < 256; o <<= 1) {
        int x = (t >= o) ? s[t - o] : 0;
        __syncthreads();
        s[t] += x;
        __syncthreads();
    }
    if (t == 0) s_boff = (blockIdx.x == 0) ? 0 : s[blockIdx.x - 1];
    __syncthreads();
    int boff = s_boff;
    __syncthreads();
    int i = blockIdx.x * 256 + t;
    int c = (i < NN) ? g_counts[i] : 0;
    s[t] = c;
    __syncthreads();
    for (int o = 1; o < 256; o <<= 1) {
        int x = (t >= o) ? s[t - o] : 0;
        __syncthreads();
        s[t] += x;
        __syncthreads();
    }
    int excl = s[t] - c + boff;
    if (i < NN) { g_rowptr[i] = excl; g_cursor[i] = excl; }
    if (i == 0) g_rowptr[NN] = EP;
}

// ---------------- launch 4: scatter + counts re-zero -------------------------
__global__ void k_scatter(const void* ei) {
    __shared__ int s_is64;
    if (threadIdx.x == 0) s_is64 = sniff64(ei);
    __syncthreads();
    int i = blockIdx.x * blockDim.x + threadIdx.x;
    if (i < NN) g_counts[i] = 0;        // restore invariant for next replay
    if (i >= EP) return;
    int is64 = s_is64;
    int s, d;
    if (i < EE) {
        s = eidx(ei, i, is64);
        d = eidx(ei, (long long)EE + i, is64);
    } else {
        s = d = i - EE;
    }
    int pos = atomicAdd(&g_cursor[d], 1);
    g_esrc[pos] = s;
}

// ---------------- GEMM1 + attn-logits: persistent fp16 mma -------------------
#define SAS 136
#define SAF 132
#define OFF_B  0
#define OFF_FA (256 * SAS * 2)
#define OFF_HA (OFF_FA + 32 * SAF * 4)
#define SM_BYTES (OFF_HA + 32 * SAS * 2)        // 95232 B

__device__ __forceinline__ uint32_t cvta_s(const void* p) {
    uint32_t a;
    asm("{ .reg .u64 t; cvta.to.shared.u64 t, %1; cvt.u32.u64 %0, t; }" : "=r"(a) : "l"(p));
    return a;
}
__device__ __forceinline__ void ldmx4(uint32_t r[4], uint32_t addr) {
    asm volatile("ldmatrix.sync.aligned.m8n8.x4.shared.b16 {%0,%1,%2,%3}, [%4];"
                 : "=r"(r[0]), "=r"(r[1]), "=r"(r[2]), "=r"(r[3]) : "r"(addr));
}
__device__ __forceinline__ void mma16816(float c[4], const uint32_t a[4], const uint32_t b[2]) {
    asm volatile(
        "mma.sync.aligned.m16n8k16.row.col.f32.f16.f16.f32 "
        "{%0,%1,%2,%3},{%4,%5,%6,%7},{%8,%9},{%0,%1,%2,%3};"
        : "+f"(c[0]), "+f"(c[1]), "+f"(c[2]), "+f"(c[3])
        : "r"(a[0]), "r"(a[1]), "r"(a[2]), "r"(a[3]), "r"(b[0]), "r"(b[1]));
}
#define CPASYNC16(dst, src) \
    asm volatile("cp.async.ca.shared.global [%0], [%1], 16;" :: "r"(dst), "l"(src))
#define CPCOMMIT() asm volatile("cp.async.commit_group;" ::: "memory")
#define CPWAIT0()  asm volatile("cp.async.wait_group 0;" ::: "memory")

__device__ __forceinline__ void issue_a(uint32_t sbase, const float* __restrict__ x,
                                        int t, int arow, int acol) {
    int gr = t * 32 + arow;
    if (gr >= NN) gr = NN - 1;
    const float* src = x + (size_t)gr * KIN + acol;
    uint32_t dst = sbase + OFF_FA + (uint32_t)((arow * SAF + acol) * 4);
#pragma unroll
    for (int j = 0; j < 4; j++) CPASYNC16(dst + j * 16, src + j * 4);
}

__device__ __forceinline__ void cvt_a(char* smc, int tid) {
    const float* fb = (const float*)(smc + OFF_FA);
    __half* hb = (__half*)(smc + OFF_HA);
#pragma unroll
    for (int j = tid; j < 1024; j += 256) {
        int row = j >> 5, c4 = (j & 31) * 4;
        float4 v = *(const float4*)(fb + row * SAF + c4);
        *(uint2*)(hb + row * SAS + c4) = pack4h(v);
    }
}

__global__ void __launch_bounds__(256, 2) k_hmma1(const float* __restrict__ x,
                                                  const float* __restrict__ asrc,
                                                  const float* __restrict__ adst) {
    extern __shared__ char smc[];
    __half* smB = (__half*)smc;
    uint32_t sbase = cvta_s(smc);
    int tid = threadIdx.x;
    int wid = tid >> 5, lane = tid & 31;
    int wm = wid >> 2, wn = wid & 3;
    int cx = blockIdx.x;
    int hA = 2 * wn, hB = 2 * wn + 1;

    int arow = tid >> 3;
    int acol = (tid & 7) * 16;
    const int T = (NN + 31) / 32;

    int t = cx;
    issue_a(sbase, x, t, arow, acol);
    CPCOMMIT();

    for (int i = tid; i < 4096; i += 256) {
        int n = i >> 4, k8 = (i & 15) * 8;
        *(uint4*)(smB + n * SAS + k8) =
            *(const uint4*)(g_Wh + (size_t)n * KIN + k8);
    }

    float saA[8], daA[8], saB[8], daB[8];
#pragma unroll
    for (int j8 = 0; j8 < 4; j8++)
#pragma unroll
        for (int j = 0; j < 2; j++) {
            int c = j8 * 8 + (lane & 3) * 2 + j;
            saA[j8 * 2 + j] = asrc[hA * HD + c];
            daA[j8 * 2 + j] = adst[hA * HD + c];
            saB[j8 * 2 + j] = asrc[hB * HD + c];
            daB[j8 * 2 + j] = adst[hB * HD + c];
        }

    int blk = lane >> 3, rowin = lane & 7;
    int a_r = (blk & 1) * 8 + rowin, a_c = (blk >> 1) * 8;
    int b_n = (blk >> 1) * 8 + rowin, b_c = (blk & 1) * 8;

    CPWAIT0();
    __syncthreads();
    cvt_a(smc, tid);
    __syncthreads();

    for (; t < T; t += GRID1) {
        int tn = t + GRID1;
        bool have_next = (tn < T);
        if (have_next) {
            issue_a(sbase, x, tn, arow, acol);
            CPCOMMIT();
        }

        float acc[8][4] = {};
#pragma unroll
        for (int ks = 0; ks < 8; ks++) {
            int k0 = ks * 16;
            uint32_t a4[4], b4[4][4];
            uint32_t aoff = sbase + OFF_HA +
                            (uint32_t)(((wm * 16 + a_r) * SAS + k0 + a_c) * 2);
            ldmx4(a4, aoff);
#pragma unroll
            for (int pr = 0; pr < 4; pr++) {
                int nB = wn * 64 + pr * 16 + b_n;
                uint32_t boff = sbase + (uint32_t)((nB * SAS + k0 + b_c) * 2);
                ldmx4(b4[pr], boff);
            }
#pragma unroll
            for (int nt = 0; nt < 8; nt++)
                mma16816(acc[nt], a4, &b4[nt >> 1][(nt & 1) * 2]);
        }

        {
            float sA0 = 0.f, dA0 = 0.f, sA8 = 0.f, dA8 = 0.f;
            float sB0 = 0.f, dB0 = 0.f, sB8 = 0.f, dB8 = 0.f;
#pragma unroll
            for (int j8 = 0; j8 < 4; j8++) {
                sA0 += acc[j8][0] * saA[j8 * 2] + acc[j8][1] * saA[j8 * 2 + 1];
                dA0 += acc[j8][0] * daA[j8 * 2] + acc[j8][1] * daA[j8 * 2 + 1];
                sA8 += acc[j8][2] * saA[j8 * 2] + acc[j8][3] * saA[j8 * 2 + 1];
                dA8 += acc[j8][2] * daA[j8 * 2] + acc[j8][3] * daA[j8 * 2 + 1];
                sB0 += acc[4 + j8][0] * saB[j8 * 2] + acc[4 + j8][1] * saB[j8 * 2 + 1];
                dB0 += acc[4 + j8][0] * daB[j8 * 2] + acc[4 + j8][1] * daB[j8 * 2 + 1];
                sB8 += acc[4 + j8][2] * saB[j8 * 2] + acc[4 + j8][3] * saB[j8 * 2 + 1];
                dB8 += acc[4 + j8][2] * daB[j8 * 2] + acc[4 + j8][3] * daB[j8 * 2 + 1];
            }
#pragma unroll
            for (int o = 1; o <= 2; o <<= 1) {
                sA0 += __shfl_xor_sync(0xffffffffu, sA0, o);
                dA0 += __shfl_xor_sync(0xffffffffu, dA0, o);
                sA8 += __shfl_xor_sync(0xffffffffu, sA8, o);
                dA8 += __shfl_xor_sync(0xffffffffu, dA8, o);
                sB0 += __shfl_xor_sync(0xffffffffu, sB0, o);
                dB0 += __shfl_xor_sync(0xffffffffu, dB0, o);
                sB8 += __shfl_xor_sync(0xffffffffu, sB8, o);
                dB8 += __shfl_xor_sync(0xffffffffu, dB8, o);
            }
            if ((lane & 3) == 0) {
                int r = t * 32 + wm * 16 + (lane >> 2);
                if (r < NN) {
                    g_as1[r * NH + hA] = sA0; g_ad1[r * NH + hA] = dA0;
                    g_as1[r * NH + hB] = sB0; g_ad1[r * NH + hB] = dB0;
                }
                if (r + 8 < NN) {
                    g_as1[(r + 8) * NH + hA] = sA8; g_ad1[(r + 8) * NH + hA] = dA8;
                    g_as1[(r + 8) * NH + hB] = sB8; g_ad1[(r + 8) * NH + hB] = dB8;
                }
            }
        }

        int r = t * 32 + wm * 16 + (lane >> 2);
#pragma unroll
        for (int nt = 0; nt < 8; nt++) {
            int gc = wn * 64 + nt * 8 + (lane & 3) * 2;
            if (r < NN)
                *(__half2*)(g_h1h + (size_t)r * C1 + gc) =
                    __floats2half2_rn(acc[nt][0], acc[nt][1]);
            if (r + 8 < NN)
                *(__half2*)(g_h1h + (size_t)(r + 8) * C1 + gc) =
                    __floats2half2_rn(acc[nt][2], acc[nt][3]);
        }

        if (have_next) CPWAIT0();
        __syncthreads();
        if (have_next) cvt_a(smc, tid);
        __syncthreads();
    }
}

// ---------------- layer-1 aggregation: 1 warp/node, uint4 (8ch) per lane -----
__global__ void k_agg1(const float* __restrict__ b1) {
    int warp = (blockIdx.x * blockDim.x + threadIdx.x) >> 5;
    if (warp >= NN) return;
    int lane = threadIdx.x & 31;
    int n = warp;
    int head = lane >> 2;              // 0..7
    int beg = g_rowptr[n], end = g_rowptr[n + 1];
    float ad = g_ad1[n * NH + head];

    float acc[8] = {};
    float den = 0.f;
    int i = beg;
    for (; i + 3 < end; i += 4) {
        int s0 = g_esrc[i], s1 = g_esrc[i + 1], s2 = g_esrc[i + 2], s3 = g_esrc[i + 3];
        float a0 = g_as1[s0 * NH + head], a1 = g_as1[s1 * NH + head];
        float a2 = g_as1[s2 * NH + head], a3 = g_as1[s3 * NH + head];
        uint4 u0 = ((const uint4*)(g_h1h + (size_t)s0 * C1))[lane];
        uint4 u1 = ((const uint4*)(g_h1h + (size_t)s1 * C1))[lane];
        uint4 u2 = ((const uint4*)(g_h1h + (size_t)s2 * C1))[lane];
        uint4 u3 = ((const uint4*)(g_h1h + (size_t)s3 * C1))[lane];
        float w0 = __expf(lrelu(a0 + ad)), w1 = __expf(lrelu(a1 + ad));
        float w2 = __expf(lrelu(a2 + ad)), w3 = __expf(lrelu(a3 + ad));
        den += w0 + w1 + w2 + w3;
        const uint32_t* p0 = (const uint32_t*)&u0;
        const uint32_t* p1 = (const uint32_t*)&u1;
        const uint32_t* p2 = (const uint32_t*)&u2;
        const uint32_t* p3 = (const uint32_t*)&u3;
#pragma unroll
        for (int q = 0; q < 4; q++) {
            float2 f0 = __half22float2(*(__half2*)&p0[q]);
            float2 f1 = __half22float2(*(__half2*)&p1[q]);
            float2 f2 = __half22float2(*(__half2*)&p2[q]);
            float2 f3 = __half22float2(*(__half2*)&p3[q]);
            acc[2 * q]     += w0 * f0.x + w1 * f1.x + w2 * f2.x + w3 * f3.x;
            acc[2 * q + 1] += w0 * f0.y + w1 * f1.y + w2 * f2.y + w3 * f3.y;
        }
    }
    for (; i < end; i++) {
        int s = g_esrc[i];
        float a = g_as1[s * NH + head];
        uint4 u = ((const uint4*)(g_h1h + (size_t)s * C1))[lane];
        float w = __expf(lrelu(a + ad));
        den += w;
        const uint32_t* p = (const uint32_t*)&u;
#pragma unroll
        for (int q = 0; q < 4; q++) {
            float2 f = __half22float2(*(__half2*)&p[q]);
            acc[2 * q]     += w * f.x;
            acc[2 * q + 1] += w * f.y;
        }
    }
    float inv = 1.f / den;
    float4 bb0 = ((const float4*)b1)[lane * 2];
    float4 bb1 = ((const float4*)b1)[lane * 2 + 1];
    float o[8];
    o[0] = elu1(acc[0] * inv + bb0.x); o[1] = elu1(acc[1] * inv + bb0.y);
    o[2] = elu1(acc[2] * inv + bb0.z); o[3] = elu1(acc[3] * inv + bb0.w);
    o[4] = elu1(acc[4] * inv + bb1.x); o[5] = elu1(acc[5] * inv + bb1.y);
    o[6] = elu1(acc[6] * inv + bb1.z); o[7] = elu1(acc[7] * inv + bb1.w);
    uint4 st;
    {
        __half2 h0 = __floats2half2_rn(o[0], o[1]);
        __half2 h1 = __floats2half2_rn(o[2], o[3]);
        __half2 h2 = __floats2half2_rn(o[4], o[5]);
        __half2 h3 = __floats2half2_rn(o[6], o[7]);
        st.x = *(uint32_t*)&h0; st.y = *(uint32_t*)&h1;
        st.z = *(uint32_t*)&h2; st.w = *(uint32_t*)&h3;
    }
    ((uint4*)(g_h1outh + (size_t)n * C1))[lane] = st;
}

// ---------------- GEMM2 (fused W2aug, fp16 input) ----------------------------
__global__ void k_gemm2(const float* __restrict__ W2,
                        const float* __restrict__ as2,
                        const float* __restrict__ ad2) {
    __shared__ float Ws[C1 * 12];
    for (int i = threadIdx.x; i < C1; i += blockDim.x) {
        float s = 0.f, d = 0.f;
#pragma unroll
        for (int c = 0; c < NC; c++) {
            float w = W2[i * NC + c];
            Ws[i * 12 + c] = w;
            s += w * as2[c];
            d += w * ad2[c];
        }
        Ws[i * 12 + 10] = s;
        Ws[i * 12 + 11] = d;
    }
    __syncthreads();
    int n = blockIdx.x * blockDim.x + threadIdx.x;
    if (n >= NN) return;
    float acc[12];
#pragma unroll
    for (int c = 0; c < 12; c++) acc[c] = 0.f;
    const uint4* xp = (const uint4*)(g_h1outh + (size_t)n * C1);
    for (int q = 0; q < 32; q++) {
        uint4 u = xp[q];
        float f[8];
        float2 t0 = __half22float2(*(__half2*)&u.x);
        float2 t1 = __half22float2(*(__half2*)&u.y);
        float2 t2 = __half22float2(*(__half2*)&u.z);
        float2 t3 = __half22float2(*(__half2*)&u.w);
        f[0] = t0.x; f[1] = t0.y; f[2] = t1.x; f[3] = t1.y;
        f[4] = t2.x; f[5] = t2.y; f[6] = t3.x; f[7] = t3.y;
        const float* w = &Ws[(q * 8) * 12];
#pragma unroll
        for (int k = 0; k < 8; k++)
#pragma unroll
            for (int c = 0; c < 12; c++)
                acc[c] += f[k] * w[k * 12 + c];
    }
#pragma unroll
    for (int c = 0; c < 12; c++) g_h2[n * 12 + c] = acc[c];
}

// ---------------- layer-2 agg + log-softmax: thread-per-node, no shfl --------
__global__ void k_agg2(const float* __restrict__ b2, float* __restrict__ out) {
    int n = blockIdx.x * blockDim.x + threadIdx.x;
    if (n >= NN) return;
    float ad2v = g_h2[n * 12 + 11];
    int beg = g_rowptr[n], end = g_rowptr[n + 1];

    float acc[NC] = {};
    float den = 0.f;
    int i = beg;
    for (; i + 1 < end; i += 2) {            // unroll x2: two gathers in flight
        int s0 = g_esrc[i], s1 = g_esrc[i + 1];
        const float4* hp0 = (const float4*)(g_h2 + (size_t)s0 * 12);
        const float4* hp1 = (const float4*)(g_h2 + (size_t)s1 * 12);
        float4 a0 = hp0[0], a1 = hp0[1], a2 = hp0[2];
        float4 b0 = hp1[0], b1 = hp1[1], b2v = hp1[2];
        float w0 = __expf(lrelu(a2.z + ad2v));
        float w1 = __expf(lrelu(b2v.z + ad2v));
        den += w0 + w1;
        acc[0] += w0 * a0.x + w1 * b0.x; acc[1] += w0 * a0.y + w1 * b0.y;
        acc[2] += w0 * a0.z + w1 * b0.z; acc[3] += w0 * a0.w + w1 * b0.w;
        acc[4] += w0 * a1.x + w1 * b1.x; acc[5] += w0 * a1.y + w1 * b1.y;
        acc[6] += w0 * a1.z + w1 * b1.z; acc[7] += w0 * a1.w + w1 * b1.w;
        acc[8] += w0 * a2.x + w1 * b2v.x; acc[9] += w0 * a2.y + w1 * b2v.y;
    }
    for (; i < end; i++) {
        int s = g_esrc[i];
        const float4* hp = (const float4*)(g_h2 + (size_t)s * 12);
        float4 r0 = hp[0], r1 = hp[1], r2 = hp[2];
        float w = __expf(lrelu(r2.z + ad2v));
        den += w;
        acc[0] += w * r0.x; acc[1] += w * r0.y; acc[2] += w * r0.z; acc[3] += w * r0.w;
        acc[4] += w * r1.x; acc[5] += w * r1.y; acc[6] += w * r1.z; acc[7] += w * r1.w;
        acc[8] += w * r2.x; acc[9] += w * r2.y;
    }
    float inv = 1.f / den;
    float v[NC];
#pragma unroll
    for (int c = 0; c < NC; c++) v[c] = acc[c] * inv + b2[c];
    float mx = v[0];
#pragma unroll
    for (int c = 1; c < NC; c++) mx = fmaxf(mx, v[c]);
    float sm = 0.f;
#pragma unroll
    for (int c = 0; c < NC; c++) sm += __expf(v[c] - mx);
    float l = mx + __logf(sm);
#pragma unroll
    for (int c = 0; c < NC; c++) out[(size_t)n * NC + c] = v[c] - l;
}

// ---------------- launch ----------------
extern "C" void kernel_launch(void* const* d_in, const int* in_sizes, int n_in,
                              void* d_out, int out_size) {
    const float* x   = (const float*)d_in[0];
    const void*  ei  = d_in[1];
    const float* W1  = (const float*)d_in[2];
    const float* as1 = (const float*)d_in[3];
    const float* ad1 = (const float*)d_in[4];
    const float* b1  = (const float*)d_in[5];
    const float* W2  = (const float*)d_in[6];
    const float* as2 = (const float*)d_in[7];
    const float* ad2 = (const float*)d_in[8];
    const float* b2  = (const float*)d_in[9];
    float* out = (float*)d_out;

    cudaFuncSetAttribute(k_hmma1, cudaFuncAttributeMaxDynamicSharedMemorySize, SM_BYTES);

    k_prep<<<(EP + 255) / 256, 256>>>(ei, W1);              // 1
    k_scan1<<<196, 256>>>();                                // 2
    k_scan3<<<196, 256>>>();                                // 3
    k_scatter<<<(EP + 255) / 256, 256>>>(ei);               // 4 <- ncu slot
    k_hmma1<<<GRID1, 256, SM_BYTES>>>(x, as1, ad1);         // 5
    k_agg1<<<(NN + 7) / 8, 256>>>(b1);                      // 6
    k_gemm2<<<(NN + 127) / 128, 128>>>(W2, as2, ad2);       // 7
    k_agg2<<<(NN + 255) / 256, 256>>>(b2, out);             // 8
}